// round 9
// baseline (speedup 1.0000x reference)
#include <cuda_runtime.h>
#include <stdint.h>

#define GRID_N 256

// dx = fp32(20/255); R = fp32(1/dx). XLA rewrites A/dx -> A*(1/dx), constant-folded.
#define DXF (20.0f / 255.0f)
#define RF  (1.0f / DXF)

__device__ __forceinline__ void red_add_evict_last(float* addr, float v, uint64_t policy)
{
    asm volatile("red.global.add.L2::cache_hint.f32 [%0], %1, %2;"
                 :: "l"(addr), "f"(v), "l"(policy) : "memory");
}

__device__ __forceinline__ uint64_t make_evict_last_policy()
{
    uint64_t p;
    asm("createpolicy.fractional.L2::evict_last.b64 %0, 1.0;" : "=l"(p));
    return p;
}

__device__ __forceinline__ void prefetch_l2(const float* addr)
{
    asm volatile("prefetch.global.L2 [%0];" :: "l"(addr));
}

// Compute flat cell index for one particle; returns -1 if out of grid.
__device__ __forceinline__ int cell_index(float px, float py, float pz)
{
    // fi = (p + 10) * R ; then fi + 0.5, trunc toward zero.
    // __fmul_rn/__fadd_rn forbid FFMA contraction (XLA emits separate mul/add).
    float fx = __fadd_rn(__fmul_rn(__fadd_rn(px, 10.0f), RF), 0.5f);
    float fy = __fadd_rn(__fmul_rn(__fadd_rn(py, 10.0f), RF), 0.5f);
    float fz = __fadd_rn(__fmul_rn(__fadd_rn(pz, 10.0f), RF), 0.5f);

    int ix = (int)fx;   // cvt.rzi: trunc toward zero == astype(int32)
    int iy = (int)fy;
    int iz = (int)fz;

    bool in_grid = (ix >= 0) & (ix < GRID_N) &
                   (iy >= 0) & (iy < GRID_N) &
                   (iz >= 0) & (iz < GRID_N);
    return in_grid ? (ix * GRID_N + iy) * GRID_N + iz : -1;
}

// Load one float4-group (4 particles) and produce 4 (index, weight) pairs.
__device__ __forceinline__ void load_batch(
    const float4* __restrict__ p4, const float4* __restrict__ w4, int g,
    int idx[4], float wt[4])
{
    float4 a = __ldcs(&p4[3 * g + 0]);
    float4 b = __ldcs(&p4[3 * g + 1]);
    float4 c = __ldcs(&p4[3 * g + 2]);
    float4 w = __ldcs(&w4[g]);

    idx[0] = cell_index(a.x, a.y, a.z); wt[0] = w.x;
    idx[1] = cell_index(a.w, b.x, b.y); wt[1] = w.y;
    idx[2] = cell_index(b.z, b.w, c.x); wt[2] = w.z;
    idx[3] = cell_index(c.y, c.z, c.w); wt[3] = w.w;
}

__global__ void __launch_bounds__(256) scatter_kernel_pf(
    const float* __restrict__ positions,  // [N,3]
    const float* __restrict__ weights,    // [N]
    float* __restrict__ grid,
    int n_groups,       // number of complete 4-particle groups
    int n_particles)
{
    const float4* p4 = (const float4*)positions;
    const float4* w4 = (const float4*)weights;
    uint64_t policy = make_evict_last_policy();

    int stride = gridDim.x * blockDim.x;
    int t = blockIdx.x * blockDim.x + threadIdx.x;

    int cur_idx[4];
    float cur_wt[4];
    bool have = false;

    // Software pipeline: prefetch batch g's grid lines, deposit batch g-1.
    for (int g = t; g < n_groups; g += stride) {
        int nidx[4];
        float nwt[4];
        load_batch(p4, w4, g, nidx, nwt);
        #pragma unroll
        for (int j = 0; j < 4; j++)
            if (nidx[j] >= 0) prefetch_l2(&grid[nidx[j]]);

        if (have) {
            #pragma unroll
            for (int j = 0; j < 4; j++)
                if (cur_idx[j] >= 0) red_add_evict_last(&grid[cur_idx[j]], cur_wt[j], policy);
        }
        #pragma unroll
        for (int j = 0; j < 4; j++) { cur_idx[j] = nidx[j]; cur_wt[j] = nwt[j]; }
        have = true;
    }
    if (have) {
        #pragma unroll
        for (int j = 0; j < 4; j++)
            if (cur_idx[j] >= 0) red_add_evict_last(&grid[cur_idx[j]], cur_wt[j], policy);
    }

    // Tail particles (n_particles not divisible by 4): handled by thread 0's lane range.
    int tail_start = n_groups * 4;
    for (int i = tail_start + t; i < n_particles; i += stride) {
        float px = __ldcs(&positions[3 * i + 0]);
        float py = __ldcs(&positions[3 * i + 1]);
        float pz = __ldcs(&positions[3 * i + 2]);
        float w  = __ldcs(&weights[i]);
        int idx = cell_index(px, py, pz);
        if (idx >= 0) red_add_evict_last(&grid[idx], w, policy);
    }
}

extern "C" void kernel_launch(void* const* d_in, const int* in_sizes, int n_in,
                              void* d_out, int out_size)
{
    const float* positions = (const float*)d_in[0];
    const float* weights   = (const float*)d_in[1];
    float* grid            = (float*)d_out;

    int n_particles = in_sizes[1];  // weights has N elements; positions has 3N
    int n_groups = n_particles / 4;

    cudaMemsetAsync(grid, 0, (size_t)out_size * sizeof(float), 0);

    // One full wave: 148 SMs x 8 CTAs (256 thr, 24-ish regs -> 8 CTAs fits 64-warp cap)
    int threads = 256;
    int blocks = 148 * 8;
    scatter_kernel_pf<<<blocks, threads>>>(positions, weights, grid, n_groups, n_particles);
}

// round 11
// speedup vs baseline: 1.3687x; 1.3687x over previous
#include <cuda_runtime.h>
#include <stdint.h>

#define GRID_N 256
#define GRID_CELLS (GRID_N * GRID_N * GRID_N)

// dx = fp32(20/255); R = fp32(1/dx). XLA rewrites A/dx -> A*(1/dx), constant-folded.
#define DXF (20.0f / 255.0f)
#define RF  (1.0f / DXF)

__device__ __forceinline__ uint64_t make_evict_last_policy()
{
    uint64_t p;
    asm("createpolicy.fractional.L2::evict_last.b64 %0, 1.0;" : "=l"(p));
    return p;
}

__device__ __forceinline__ void red_add_evict_last(float* addr, float v, uint64_t policy)
{
    asm volatile("red.global.add.L2::cache_hint.f32 [%0], %1, %2;"
                 :: "l"(addr), "f"(v), "l"(policy) : "memory");
}

__device__ __forceinline__ void st_zero4_evict_last(float4* addr, uint64_t policy)
{
    asm volatile("st.global.L2::cache_hint.v4.f32 [%0], {%1, %1, %1, %1}, %2;"
                 :: "l"(addr), "f"(0.0f), "l"(policy) : "memory");
}

// Zero the grid with evict_last priority so every grid line sits in L2 at top
// retention priority BEFORE the particle stream starts competing for capacity.
__global__ void __launch_bounds__(256) zero_grid_kernel(float* __restrict__ grid, int n_cells)
{
    uint64_t policy = make_evict_last_policy();
    int t = blockIdx.x * blockDim.x + threadIdx.x;
    int stride = gridDim.x * blockDim.x;
    int n4 = n_cells / 4;   // GRID_CELLS divisible by 4
    float4* g4 = (float4*)grid;
    for (int i = t; i < n4; i += stride)
        st_zero4_evict_last(&g4[i], policy);
}

__device__ __forceinline__ void deposit(float px, float py, float pz, float w,
                                        float* __restrict__ grid, uint64_t policy)
{
    // fi = (p + 10) * R ; then fi + 0.5, trunc toward zero.
    // __fmul_rn/__fadd_rn forbid FFMA contraction (XLA emits separate mul/add).
    float fx = __fadd_rn(__fmul_rn(__fadd_rn(px, 10.0f), RF), 0.5f);
    float fy = __fadd_rn(__fmul_rn(__fadd_rn(py, 10.0f), RF), 0.5f);
    float fz = __fadd_rn(__fmul_rn(__fadd_rn(pz, 10.0f), RF), 0.5f);

    int ix = (int)fx;   // cvt.rzi: trunc toward zero == astype(int32)
    int iy = (int)fy;
    int iz = (int)fz;

    bool in_grid = (ix >= 0) & (ix < GRID_N) &
                   (iy >= 0) & (iy < GRID_N) &
                   (iz >= 0) & (iz < GRID_N);
    if (in_grid) {
        int flat = (ix * GRID_N + iy) * GRID_N + iz;
        red_add_evict_last(&grid[flat], w, policy);
    }
}

__global__ void __launch_bounds__(256) scatter_kernel_v4p(
    const float* __restrict__ positions,  // [N,3]
    const float* __restrict__ weights,    // [N]
    float* __restrict__ grid,
    int n_particles)
{
    int t = blockIdx.x * blockDim.x + threadIdx.x;
    int base = 4 * t;
    uint64_t policy = make_evict_last_policy();

    if (base + 3 < n_particles) {
        // 4 particles via 3 coalesced float4 loads + 1 float4 weights.
        // __ldcs = evict-first streaming: don't displace the grid from L2.
        const float4* p4 = (const float4*)positions;
        float4 a = __ldcs(&p4[3 * t + 0]);
        float4 b = __ldcs(&p4[3 * t + 1]);
        float4 c = __ldcs(&p4[3 * t + 2]);
        float4 w = __ldcs(&((const float4*)weights)[t]);

        deposit(a.x, a.y, a.z, w.x, grid, policy);
        deposit(a.w, b.x, b.y, w.y, grid, policy);
        deposit(b.z, b.w, c.x, w.z, grid, policy);
        deposit(c.y, c.z, c.w, w.w, grid, policy);
    } else if (base < n_particles) {
        // Tail: scalar per-particle.
        for (int i = base; i < n_particles; i++) {
            float px = __ldcs(&positions[3 * i + 0]);
            float py = __ldcs(&positions[3 * i + 1]);
            float pz = __ldcs(&positions[3 * i + 2]);
            float w  = __ldcs(&weights[i]);
            deposit(px, py, pz, w, grid, policy);
        }
    }
}

extern "C" void kernel_launch(void* const* d_in, const int* in_sizes, int n_in,
                              void* d_out, int out_size)
{
    const float* positions = (const float*)d_in[0];
    const float* weights   = (const float*)d_in[1];
    float* grid            = (float*)d_out;

    int n_particles = in_sizes[1];  // weights has N elements; positions has 3N

    // Zero + park grid in L2 with evict_last priority.
    {
        int threads = 256;
        int blocks = 148 * 8;   // one wave, grid-stride
        zero_grid_kernel<<<blocks, threads>>>(grid, out_size);
    }

    int threads = 256;
    int n_threads_total = (n_particles + 3) / 4;
    int blocks = (n_threads_total + threads - 1) / threads;
    scatter_kernel_v4p<<<blocks, threads>>>(positions, weights, grid, n_particles);
}